// round 12
// baseline (speedup 1.0000x reference)
#include <cuda_runtime.h>
#include <cuda_bf16.h>

typedef unsigned int u32;

#define NG 16
#define NTHREADS 256

// 64-pos tiles: A slot = 64 rows x 128B, hi 8K || lo 8K
#define ASLOT   16384
#define SM_B    (5 * ASLOT)            // 81920
#define BBUF    16384                  // hi 8K || lo 8K
#define SMEM_BYTES (SM_B + 2 * BBUF)   // 114688 -> 2 blocks/SM

// schedule (validated): slots 0=s0 1=s1 2=n0 3=n1 4=n2; x0->3, x1->4
__constant__ int c_in[NG]  = {3,4, 0,1, 0,1,2, 0,1,2,3, 0,1,2,3,4};
__constant__ int c_st[NG]  = {1,1, 1,0, 1,0,0, 1,0,0,0, 1,0,0,0,0};
__constant__ int c_fin[NG] = {0,1, -1,2, -1,-1,3, -1,-1,-1,4, -1,-1,-1,-1,5};

// [g]: pre-swizzled SW128 B-tile image (rows=o, 128B), hi 8KB || lo 8KB
__device__ __align__(16) unsigned char g_bsp[NG * 16384];

__device__ __forceinline__ u32 sw128(u32 o) { return o ^ ((o >> 3) & 0x70); }

__device__ __forceinline__ void split8(const float* f, uint4& hv, uint4& lv) {
    u32 h[4], l[4];
#pragma unroll
    for (int j = 0; j < 4; ++j) {
        float a = f[2*j], b = f[2*j+1];
        u32 hp;
        asm("cvt.rn.bf16x2.f32 %0, %1, %2;" : "=r"(hp) : "f"(b), "f"(a));
        float ra = a - __uint_as_float(hp << 16);
        float rb = b - __uint_as_float(hp & 0xFFFF0000u);
        u32 lp;
        asm("cvt.rn.bf16x2.f32 %0, %1, %2;" : "=r"(lp) : "f"(rb), "f"(ra));
        h[j] = hp; l[j] = lp;
    }
    hv = make_uint4(h[0], h[1], h[2], h[3]);
    lv = make_uint4(l[0], l[1], l[2], l[3]);
}

__device__ __forceinline__ void split2(float v0, float v1, u32& hp, u32& lp) {
    asm("cvt.rn.bf16x2.f32 %0, %1, %2;" : "=r"(hp) : "f"(v1), "f"(v0));
    float r0 = v0 - __uint_as_float(hp << 16);
    float r1 = v1 - __uint_as_float(hp & 0xFFFF0000u);
    asm("cvt.rn.bf16x2.f32 %0, %1, %2;" : "=r"(lp) : "f"(r1), "f"(r0));
}

__global__ void prep_weights_kernel(const float* __restrict__ Wpre,
                                    const float* __restrict__ Wedge) {
    int idx = blockIdx.x * blockDim.x + threadIdx.x;   // g*64 + o
    if (idx >= NG * 64) return;
    int g = idx >> 6, o = idx & 63;
    const float* wrow = (g < 2 ? Wpre + g * 4096 : Wedge + (g - 2) * 4096)
                        + o * 64;
    unsigned char* base = g_bsp + g * 16384;
#pragma unroll
    for (int i = 0; i < 8; ++i) {
        float f[8];
#pragma unroll
        for (int j = 0; j < 8; ++j) f[j] = wrow[i * 8 + j];
        uint4 hv, lv;
        split8(f, hv, lv);
        u32 off = sw128((u32)(o * 128 + i * 16));
        *reinterpret_cast<uint4*>(base + off) = hv;
        *reinterpret_cast<uint4*>(base + 8192 + off) = lv;
    }
}

__device__ __forceinline__ void ldm_x4(u32 a, u32* r) {
    asm volatile("ldmatrix.sync.aligned.m8n8.x4.shared.b16 {%0,%1,%2,%3}, [%4];"
        : "=r"(r[0]), "=r"(r[1]), "=r"(r[2]), "=r"(r[3]) : "r"(a));
}
__device__ __forceinline__ void mma16816(float* d, const u32* a, const u32* b) {
    asm volatile(
        "mma.sync.aligned.m16n8k16.row.col.f32.bf16.bf16.f32 "
        "{%0,%1,%2,%3},{%4,%5,%6,%7},{%8,%9},{%0,%1,%2,%3};"
        : "+f"(d[0]), "+f"(d[1]), "+f"(d[2]), "+f"(d[3])
        : "r"(a[0]), "r"(a[1]), "r"(a[2]), "r"(a[3]), "r"(b[0]), "r"(b[1]));
}

__global__ void __launch_bounds__(NTHREADS, 2)
dag_kernel(const float* __restrict__ x0, const float* __restrict__ x1,
           float* __restrict__ out) {
    extern __shared__ __align__(1024) unsigned char sm[];
    u32 smb;
    asm("{.reg .u64 t; cvta.to.shared.u64 t, %1; cvt.u32.u64 %0, t;}"
        : "=r"(smb) : "l"(sm));

    const int tid  = threadIdx.x;
    const int lane = tid & 31;
    const int wid  = tid >> 5;
    const int b    = blockIdx.x >> 4;
    const int p0   = (blockIdx.x & 15) * 64;

    // --- stage x0 -> slot3, x1 -> slot4 (2 threads per position row)
    {
        const int half = tid >> 7;
        const int r    = tid & 127;
        const int p    = r >> 1;
        const int ci   = r & 1;
        const float* gx = (half ? x1 : x0) + b * 65536 + p0 + p;
        unsigned char* slot = sm + (3 + half) * ASLOT;
        const u32 xm = (u32)((p & 7) << 4);
#pragma unroll
        for (int i = 0; i < 4; ++i) {
            const int ii = ci * 4 + i;
            float f[8];
#pragma unroll
            for (int j = 0; j < 8; ++j) f[j] = gx[(ii * 8 + j) * 1024];
            uint4 hv, lv;
            split8(f, hv, lv);
            u32 off = (u32)(p * 128) + (((u32)(ii * 16)) ^ xm);
            *reinterpret_cast<uint4*>(slot + off) = hv;
            *reinterpret_cast<uint4*>(slot + 8192 + off) = lv;
        }
    }

    // --- B prologue: B0 -> buf0; B1 prefetched into br
    uint4 br[4];
    {
        const uint4* s0 = reinterpret_cast<const uint4*>(g_bsp);
        uint4 t0[4];
#pragma unroll
        for (int j = 0; j < 4; ++j) t0[j] = s0[tid + j * 256];
        uint4* d0 = reinterpret_cast<uint4*>(sm + SM_B);
#pragma unroll
        for (int j = 0; j < 4; ++j) d0[tid + j * 256] = t0[j];
        const uint4* s1 = reinterpret_cast<const uint4*>(g_bsp + 16384);
#pragma unroll
        for (int j = 0; j < 4; ++j) br[j] = s1[tid + j * 256];
    }
    __syncthreads();

    // --- warp mapping: 2m x 2n x 2k; warp = 32 pos x 32 out, half K
    const int kh = wid >> 2;
    const int m0 = (wid & 1) * 32;
    const int n0 = ((wid >> 1) & 1) * 32;
    const int arow  = m0 + (lane & 15);
    const int acolb = (lane >> 4) * 16;
    const int brow4 = n0 + ((lane >> 4) << 3) + (lane & 7);
    const int bcolb = ((lane >> 3) & 1) * 16;
    const u32 axm = (u32)((lane & 7) << 4);
    const int prow = lane >> 2;
    const int pcol = (lane & 3) * 2;
    const u32 pxm = (u32)(prow << 4);

    float d[2][4][4];

#pragma unroll 1
    for (int g = 0; g < NG; ++g) {
        if (c_st[g]) {
#pragma unroll
            for (int mt = 0; mt < 2; ++mt)
#pragma unroll
                for (int nt = 0; nt < 4; ++nt)
#pragma unroll
                    for (int e = 0; e < 4; ++e) d[mt][nt][e] = 0.f;
        }
        // --- GEMM (k-half): d += A[kh] x B[kh]^T
        //     pass-major MMA order: 8 independent accumulators between
        //     successive writes to the same d[mt][nt] (hides HMMA latency)
        {
            const u32 ah_b = smb + c_in[g] * ASLOT;
            const u32 al_b = ah_b + 8192;
            const u32 bh_b = smb + SM_B + (g & 1) * BBUF;
            const u32 bl_b = bh_b + 8192;
#pragma unroll
            for (int kk = 0; kk < 2; ++kk) {
                const int kc = kh * 2 + kk;
                const u32 akb = ((u32)(acolb + kc * 32)) ^ axm;
                const u32 bkb = ((u32)(bcolb + kc * 32)) ^ axm;
                u32 ah[2][4], al[2][4], bh[2][4], bl[2][4];
#pragma unroll
                for (int mt = 0; mt < 2; ++mt) {
                    u32 ro = (u32)((arow + mt * 16) * 128) + akb;
                    ldm_x4(ah_b + ro, ah[mt]);
                    ldm_x4(al_b + ro, al[mt]);
                }
#pragma unroll
                for (int nn = 0; nn < 2; ++nn) {
                    u32 ro = (u32)((brow4 + nn * 16) * 128) + bkb;
                    ldm_x4(bh_b + ro, bh[nn]);
                    ldm_x4(bl_b + ro, bl[nn]);
                }
                // pass 1: hi * B_hi
#pragma unroll
                for (int mt = 0; mt < 2; ++mt)
#pragma unroll
                    for (int nt = 0; nt < 4; ++nt)
                        mma16816(d[mt][nt], ah[mt], &bh[nt >> 1][(nt & 1) * 2]);
                // pass 2: hi * B_lo
#pragma unroll
                for (int mt = 0; mt < 2; ++mt)
#pragma unroll
                    for (int nt = 0; nt < 4; ++nt)
                        mma16816(d[mt][nt], ah[mt], &bl[nt >> 1][(nt & 1) * 2]);
                // pass 3: lo * B_hi
#pragma unroll
                for (int mt = 0; mt < 2; ++mt)
#pragma unroll
                    for (int nt = 0; nt < 4; ++nt)
                        mma16816(d[mt][nt], al[mt], &bh[nt >> 1][(nt & 1) * 2]);
            }
        }
        // --- state finished: reduce k-halves, raw -> global, relu -> slot
        {
            const int f = c_fin[g];
            if (f >= 0) {
                unsigned char* scr = (f <= 4) ? (sm + f * ASLOT) : (sm + SM_B);
                __syncthreads();                    // all MMA reads done
                if (kh) {                           // upper K half: dump raw
#pragma unroll
                    for (int mt = 0; mt < 2; ++mt)
#pragma unroll
                        for (int nt = 0; nt < 4; ++nt) {
                            const int p = m0 + mt * 16 + prow;
                            const int o = n0 + nt * 8 + pcol;
                            const u32 cb = ((u32)(o * 4)) ^ ((u32)(prow << 5));
                            *reinterpret_cast<float2*>(scr + p * 256 + cb) =
                                make_float2(d[mt][nt][0], d[mt][nt][1]);
                            *reinterpret_cast<float2*>(scr + (p + 8) * 256 + cb) =
                                make_float2(d[mt][nt][2], d[mt][nt][3]);
                        }
                }
                __syncthreads();
                if (!kh) {                          // lower half: add partials
#pragma unroll
                    for (int mt = 0; mt < 2; ++mt)
#pragma unroll
                        for (int nt = 0; nt < 4; ++nt) {
                            const int p = m0 + mt * 16 + prow;
                            const int o = n0 + nt * 8 + pcol;
                            const u32 cb = ((u32)(o * 4)) ^ ((u32)(prow << 5));
                            float2 u = *reinterpret_cast<const float2*>(
                                           scr + p * 256 + cb);
                            float2 v = *reinterpret_cast<const float2*>(
                                           scr + (p + 8) * 256 + cb);
                            d[mt][nt][0] += u.x; d[mt][nt][1] += u.y;
                            d[mt][nt][2] += v.x; d[mt][nt][3] += v.y;
                        }
                }
                __syncthreads();                    // reads done before reuse
                if (!kh) {
                    if (f >= 2) {
                        const int node = (f == 5) ? 3 : (f - 2);
                        float* gp = out + b * 262144 + node * 65536 + p0;
#pragma unroll
                        for (int mt = 0; mt < 2; ++mt)
#pragma unroll
                            for (int nt = 0; nt < 4; ++nt) {
                                const int o = n0 + nt * 8 + pcol;
                                const int p = m0 + mt * 16 + prow;
                                gp[o * 1024 + p]           = d[mt][nt][0];
                                gp[(o + 1) * 1024 + p]     = d[mt][nt][1];
                                gp[o * 1024 + p + 8]       = d[mt][nt][2];
                                gp[(o + 1) * 1024 + p + 8] = d[mt][nt][3];
                            }
                    }
                    if (f <= 4) {
                        unsigned char* sd = sm + f * ASLOT;
#pragma unroll
                        for (int mt = 0; mt < 2; ++mt)
#pragma unroll
                            for (int nt = 0; nt < 4; ++nt) {
                                const int p = m0 + mt * 16 + prow;
                                const int c = n0 + nt * 8 + pcol;
                                const u32 cb = ((u32)(c * 2)) ^ pxm;
                                u32 hp, lp;
                                split2(fmaxf(d[mt][nt][0], 0.f),
                                       fmaxf(d[mt][nt][1], 0.f), hp, lp);
                                u32 off = (u32)(p * 128) + cb;
                                *reinterpret_cast<u32*>(sd + off) = hp;
                                *reinterpret_cast<u32*>(sd + 8192 + off) = lp;
                                split2(fmaxf(d[mt][nt][2], 0.f),
                                       fmaxf(d[mt][nt][3], 0.f), hp, lp);
                                off = (u32)((p + 8) * 128) + cb;
                                *reinterpret_cast<u32*>(sd + off) = hp;
                                *reinterpret_cast<u32*>(sd + 8192 + off) = lp;
                            }
                    }
                }
            }
        }
        // --- B staging: STS B[g+1] (held in br), then prefetch B[g+2]
        if (g + 1 < NG) {
            uint4* dst = reinterpret_cast<uint4*>(sm + SM_B + ((g + 1) & 1) * BBUF);
#pragma unroll
            for (int j = 0; j < 4; ++j) dst[tid + j * 256] = br[j];
        }
        if (g + 2 < NG) {
            const uint4* s = reinterpret_cast<const uint4*>(g_bsp + (g + 2) * 16384);
#pragma unroll
            for (int j = 0; j < 4; ++j) br[j] = s[tid + j * 256];
        }
        __syncthreads();
    }
}

extern "C" void kernel_launch(void* const* d_in, const int* in_sizes, int n_in,
                              void* d_out, int out_size) {
    const float* x0    = (const float*)d_in[0];
    const float* x1    = (const float*)d_in[1];
    const float* Wpre  = (const float*)d_in[2];
    const float* Wedge = (const float*)d_in[3];
    float* out = (float*)d_out;

    prep_weights_kernel<<<8, 128>>>(Wpre, Wedge);

    cudaFuncSetAttribute(dag_kernel,
                         cudaFuncAttributeMaxDynamicSharedMemorySize,
                         SMEM_BYTES);
    dag_kernel<<<1024, NTHREADS, SMEM_BYTES>>>(x0, x1, out);
}

// round 13
// speedup vs baseline: 1.2604x; 1.2604x over previous
#include <cuda_runtime.h>
#include <cuda_fp16.h>

typedef unsigned int u32;

#define NG 16
#define NTHREADS 256

// 64-pos tiles: A slot = 64 rows x 128B fp16 (single plane)
#define ASLOT   8192
#define SM_B    (5 * ASLOT)            // 40960
#define BBUF    16384                  // w_hi 8K || w_lo 8K
#define SMEM_BYTES (SM_B + 2 * BBUF)   // 73728 -> 2 blocks/SM

// schedule (validated): slots 0=s0 1=s1 2=n0 3=n1 4=n2; x0->3, x1->4
__constant__ int c_in[NG]  = {3,4, 0,1, 0,1,2, 0,1,2,3, 0,1,2,3,4};
__constant__ int c_st[NG]  = {1,1, 1,0, 1,0,0, 1,0,0,0, 1,0,0,0,0};
__constant__ int c_fin[NG] = {0,1, -1,2, -1,-1,3, -1,-1,-1,4, -1,-1,-1,-1,5};

// [g]: pre-swizzled SW128 B-tile image (rows=o, 128B), w_hi 8KB || w_lo 8KB
__device__ __align__(16) unsigned char g_bsp[NG * 16384];

__device__ __forceinline__ u32 sw128(u32 o) { return o ^ ((o >> 3) & 0x70); }

__device__ __forceinline__ u32 packh2(float a, float b) {
    __half2 h = __floats2half2_rn(a, b);
    return *reinterpret_cast<u32*>(&h);
}

// split 8 fp32 -> fp16 hi/lo packed uint4 (exact two-term split)
__device__ __forceinline__ void split8h(const float* f, uint4& hv, uint4& lv) {
    u32 h[4], l[4];
#pragma unroll
    for (int j = 0; j < 4; ++j) {
        float a = f[2*j], b = f[2*j+1];
        __half ha = __float2half_rn(a), hb = __float2half_rn(b);
        h[j] = packh2(__half2float(ha), __half2float(hb));
        l[j] = packh2(a - __half2float(ha), b - __half2float(hb));
    }
    hv = make_uint4(h[0], h[1], h[2], h[3]);
    lv = make_uint4(l[0], l[1], l[2], l[3]);
}

// pack 8 fp32 -> single fp16 plane uint4
__device__ __forceinline__ uint4 pack8h(const float* f) {
    return make_uint4(packh2(f[0], f[1]), packh2(f[2], f[3]),
                      packh2(f[4], f[5]), packh2(f[6], f[7]));
}

__global__ void prep_weights_kernel(const float* __restrict__ Wpre,
                                    const float* __restrict__ Wedge) {
    int idx = blockIdx.x * blockDim.x + threadIdx.x;   // g*64 + o
    if (idx >= NG * 64) return;
    int g = idx >> 6, o = idx & 63;
    const float* wrow = (g < 2 ? Wpre + g * 4096 : Wedge + (g - 2) * 4096)
                        + o * 64;
    unsigned char* base = g_bsp + g * 16384;
#pragma unroll
    for (int i = 0; i < 8; ++i) {
        float f[8];
#pragma unroll
        for (int j = 0; j < 8; ++j) f[j] = wrow[i * 8 + j];
        uint4 hv, lv;
        split8h(f, hv, lv);
        u32 off = sw128((u32)(o * 128 + i * 16));
        *reinterpret_cast<uint4*>(base + off) = hv;
        *reinterpret_cast<uint4*>(base + 8192 + off) = lv;
    }
}

__device__ __forceinline__ void ldm_x4(u32 a, u32* r) {
    asm volatile("ldmatrix.sync.aligned.m8n8.x4.shared.b16 {%0,%1,%2,%3}, [%4];"
        : "=r"(r[0]), "=r"(r[1]), "=r"(r[2]), "=r"(r[3]) : "r"(a));
}
__device__ __forceinline__ void mma16816(float* d, const u32* a, const u32* b) {
    asm volatile(
        "mma.sync.aligned.m16n8k16.row.col.f32.f16.f16.f32 "
        "{%0,%1,%2,%3},{%4,%5,%6,%7},{%8,%9},{%0,%1,%2,%3};"
        : "+f"(d[0]), "+f"(d[1]), "+f"(d[2]), "+f"(d[3])
        : "r"(a[0]), "r"(a[1]), "r"(a[2]), "r"(a[3]), "r"(b[0]), "r"(b[1]));
}

__global__ void __launch_bounds__(NTHREADS, 2)
dag_kernel(const float* __restrict__ x0, const float* __restrict__ x1,
           float* __restrict__ out) {
    extern __shared__ __align__(1024) unsigned char sm[];
    u32 smb;
    asm("{.reg .u64 t; cvta.to.shared.u64 t, %1; cvt.u32.u64 %0, t;}"
        : "=r"(smb) : "l"(sm));

    const int tid  = threadIdx.x;
    const int lane = tid & 31;
    const int wid  = tid >> 5;
    const int b    = blockIdx.x >> 4;
    const int p0   = (blockIdx.x & 15) * 64;

    // --- stage x0 -> slot3, x1 -> slot4 (2 threads per position row)
    {
        const int half = tid >> 7;
        const int r    = tid & 127;
        const int p    = r >> 1;
        const int ci   = r & 1;
        const float* gx = (half ? x1 : x0) + b * 65536 + p0 + p;
        unsigned char* slot = sm + (3 + half) * ASLOT;
        const u32 xm = (u32)((p & 7) << 4);
#pragma unroll
        for (int i = 0; i < 4; ++i) {
            const int ii = ci * 4 + i;
            float f[8];
#pragma unroll
            for (int j = 0; j < 8; ++j) f[j] = gx[(ii * 8 + j) * 1024];
            u32 off = (u32)(p * 128) + (((u32)(ii * 16)) ^ xm);
            *reinterpret_cast<uint4*>(slot + off) = pack8h(f);
        }
    }

    // --- B prologue: B0 -> buf0; B1 prefetched into br
    uint4 br[4];
    {
        const uint4* s0 = reinterpret_cast<const uint4*>(g_bsp);
        uint4 t0[4];
#pragma unroll
        for (int j = 0; j < 4; ++j) t0[j] = s0[tid + j * 256];
        uint4* d0 = reinterpret_cast<uint4*>(sm + SM_B);
#pragma unroll
        for (int j = 0; j < 4; ++j) d0[tid + j * 256] = t0[j];
        const uint4* s1 = reinterpret_cast<const uint4*>(g_bsp + 16384);
#pragma unroll
        for (int j = 0; j < 4; ++j) br[j] = s1[tid + j * 256];
    }
    __syncthreads();

    // --- warp mapping: 2m x 2n x 2k; warp = 32 pos x 32 out, half K
    const int kh = wid >> 2;
    const int m0 = (wid & 1) * 32;
    const int n0 = ((wid >> 1) & 1) * 32;
    const int arow  = m0 + (lane & 15);
    const int acolb = (lane >> 4) * 16;
    const int brow4 = n0 + ((lane >> 4) << 3) + (lane & 7);
    const int bcolb = ((lane >> 3) & 1) * 16;
    const u32 axm = (u32)((lane & 7) << 4);
    const int prow = lane >> 2;
    const int pcol = (lane & 3) * 2;
    const u32 pxm = (u32)(prow << 4);

    float d[2][4][4];

#pragma unroll 1
    for (int g = 0; g < NG; ++g) {
        if (c_st[g]) {
#pragma unroll
            for (int mt = 0; mt < 2; ++mt)
#pragma unroll
                for (int nt = 0; nt < 4; ++nt)
#pragma unroll
                    for (int e = 0; e < 4; ++e) d[mt][nt][e] = 0.f;
        }
        // --- GEMM (k-half): d += A x (W_hi + W_lo)^T  -- 2 passes
        {
            const u32 a_b  = smb + c_in[g] * ASLOT;
            const u32 bh_b = smb + SM_B + (g & 1) * BBUF;
            const u32 bl_b = bh_b + 8192;
#pragma unroll
            for (int kk = 0; kk < 2; ++kk) {
                const int kc = kh * 2 + kk;
                const u32 akb = ((u32)(acolb + kc * 32)) ^ axm;
                const u32 bkb = ((u32)(bcolb + kc * 32)) ^ axm;
                u32 ah[2][4], bh[2][4], bl[2][4];
#pragma unroll
                for (int mt = 0; mt < 2; ++mt) {
                    u32 ro = (u32)((arow + mt * 16) * 128) + akb;
                    ldm_x4(a_b + ro, ah[mt]);
                }
#pragma unroll
                for (int nn = 0; nn < 2; ++nn) {
                    u32 ro = (u32)((brow4 + nn * 16) * 128) + bkb;
                    ldm_x4(bh_b + ro, bh[nn]);
                    ldm_x4(bl_b + ro, bl[nn]);
                }
                // pass 1: A * W_hi
#pragma unroll
                for (int mt = 0; mt < 2; ++mt)
#pragma unroll
                    for (int nt = 0; nt < 4; ++nt)
                        mma16816(d[mt][nt], ah[mt], &bh[nt >> 1][(nt & 1) * 2]);
                // pass 2: A * W_lo
#pragma unroll
                for (int mt = 0; mt < 2; ++mt)
#pragma unroll
                    for (int nt = 0; nt < 4; ++nt)
                        mma16816(d[mt][nt], ah[mt], &bl[nt >> 1][(nt & 1) * 2]);
            }
        }
        // --- state finished: reduce k-halves via just-consumed B buffer,
        //     raw -> global (nodes), relu (fp16) -> A slot
        {
            const int f = c_fin[g];
            if (f >= 0) {
                unsigned char* scr = sm + SM_B + (g & 1) * BBUF;  // 16KB free
                __syncthreads();                    // all MMA reads done
                if (kh) {                           // upper K half: dump raw
#pragma unroll
                    for (int mt = 0; mt < 2; ++mt)
#pragma unroll
                        for (int nt = 0; nt < 4; ++nt) {
                            const int p = m0 + mt * 16 + prow;
                            const int o = n0 + nt * 8 + pcol;
                            const u32 cb = ((u32)(o * 4)) ^ ((u32)(prow << 5));
                            *reinterpret_cast<float2*>(scr + p * 256 + cb) =
                                make_float2(d[mt][nt][0], d[mt][nt][1]);
                            *reinterpret_cast<float2*>(scr + (p + 8) * 256 + cb) =
                                make_float2(d[mt][nt][2], d[mt][nt][3]);
                        }
                }
                __syncthreads();
                if (!kh) {                          // lower half: add partials
#pragma unroll
                    for (int mt = 0; mt < 2; ++mt)
#pragma unroll
                        for (int nt = 0; nt < 4; ++nt) {
                            const int p = m0 + mt * 16 + prow;
                            const int o = n0 + nt * 8 + pcol;
                            const u32 cb = ((u32)(o * 4)) ^ ((u32)(prow << 5));
                            float2 u = *reinterpret_cast<const float2*>(
                                           scr + p * 256 + cb);
                            float2 v = *reinterpret_cast<const float2*>(
                                           scr + (p + 8) * 256 + cb);
                            d[mt][nt][0] += u.x; d[mt][nt][1] += u.y;
                            d[mt][nt][2] += v.x; d[mt][nt][3] += v.y;
                        }
                }
                __syncthreads();                    // reads done before reuse
                if (!kh) {
                    if (f >= 2) {
                        const int node = (f == 5) ? 3 : (f - 2);
                        float* gp = out + b * 262144 + node * 65536 + p0;
#pragma unroll
                        for (int mt = 0; mt < 2; ++mt)
#pragma unroll
                            for (int nt = 0; nt < 4; ++nt) {
                                const int o = n0 + nt * 8 + pcol;
                                const int p = m0 + mt * 16 + prow;
                                gp[o * 1024 + p]           = d[mt][nt][0];
                                gp[(o + 1) * 1024 + p]     = d[mt][nt][1];
                                gp[o * 1024 + p + 8]       = d[mt][nt][2];
                                gp[(o + 1) * 1024 + p + 8] = d[mt][nt][3];
                            }
                    }
                    if (f <= 4) {
                        unsigned char* sd = sm + f * ASLOT;
#pragma unroll
                        for (int mt = 0; mt < 2; ++mt)
#pragma unroll
                            for (int nt = 0; nt < 4; ++nt) {
                                const int p = m0 + mt * 16 + prow;
                                const int c = n0 + nt * 8 + pcol;
                                const u32 cb = ((u32)(c * 2)) ^ pxm;
                                u32 hp = packh2(fmaxf(d[mt][nt][0], 0.f),
                                                fmaxf(d[mt][nt][1], 0.f));
                                *reinterpret_cast<u32*>(
                                    sd + (u32)(p * 128) + cb) = hp;
                                hp = packh2(fmaxf(d[mt][nt][2], 0.f),
                                            fmaxf(d[mt][nt][3], 0.f));
                                *reinterpret_cast<u32*>(
                                    sd + (u32)((p + 8) * 128) + cb) = hp;
                            }
                    }
                }
            }
        }
        // --- B staging: STS B[g+1] (held in br), then prefetch B[g+2]
        if (g + 1 < NG) {
            uint4* dst = reinterpret_cast<uint4*>(sm + SM_B + ((g + 1) & 1) * BBUF);
#pragma unroll
            for (int j = 0; j < 4; ++j) dst[tid + j * 256] = br[j];
        }
        if (g + 2 < NG) {
            const uint4* s = reinterpret_cast<const uint4*>(g_bsp + (g + 2) * 16384);
#pragma unroll
            for (int j = 0; j < 4; ++j) br[j] = s[tid + j * 256];
        }
        __syncthreads();
    }
}

extern "C" void kernel_launch(void* const* d_in, const int* in_sizes, int n_in,
                              void* d_out, int out_size) {
    const float* x0    = (const float*)d_in[0];
    const float* x1    = (const float*)d_in[1];
    const float* Wpre  = (const float*)d_in[2];
    const float* Wedge = (const float*)d_in[3];
    float* out = (float*)d_out;

    prep_weights_kernel<<<8, 128>>>(Wpre, Wedge);

    cudaFuncSetAttribute(dag_kernel,
                         cudaFuncAttributeMaxDynamicSharedMemorySize,
                         SMEM_BYTES);
    dag_kernel<<<1024, NTHREADS, SMEM_BYTES>>>(x0, x1, out);
}

// round 14
// speedup vs baseline: 1.5675x; 1.2436x over previous
#include <cuda_runtime.h>
#include <cuda_fp16.h>

typedef unsigned int u32;

#define NG 16
#define NTHREADS 256

// smem: 5 A slots (64 rows x 128B fp16) + 16KB fp32 k-reduce scratch
#define ASLOT   8192
#define SM_SCR  (5 * ASLOT)            // 40960
#define SMEM_BYTES (SM_SCR + 16384)    // 57344 -> 2 blocks/SM

// schedule (validated): slots 0=s0 1=s1 2=n0 3=n1 4=n2; x0->3, x1->4
__constant__ int c_in[NG]  = {3,4, 0,1, 0,1,2, 0,1,2,3, 0,1,2,3,4};
__constant__ int c_st[NG]  = {1,1, 1,0, 1,0,0, 1,0,0,0, 1,0,0,0,0};
__constant__ int c_fin[NG] = {0,1, -1,2, -1,-1,3, -1,-1,-1,4, -1,-1,-1,-1,5};

// B fragment images in mma lane order: [g][kc][q][lane] -> {hi0,hi1,lo0,lo1}
// (emulates the validated ldmatrix x4 delivery; q = n-octet 0..7)
__device__ __align__(16) uint4 g_bf[NG * 4 * 8 * 32];   // 256 KB

__device__ __forceinline__ u32 packh2(float a, float b) {
    __half2 h = __floats2half2_rn(a, b);
    return *reinterpret_cast<u32*>(&h);
}

__global__ void prep_weights_kernel(const float* __restrict__ Wpre,
                                    const float* __restrict__ Wedge) {
    int idx = blockIdx.x * blockDim.x + threadIdx.x;
    if (idx >= NG * 4 * 8 * 32) return;
    const int lane = idx & 31;
    const int q    = (idx >> 5) & 7;
    const int kc   = (idx >> 8) & 3;
    const int g    = idx >> 10;
    const int o = q * 8 + (lane >> 2);           // output channel (B row)
    const int c = kc * 16 + (lane & 3) * 2;      // input channel (B col/k)
    const float* wrow = (g < 2 ? Wpre + g * 4096 : Wedge + (g - 2) * 4096)
                        + o * 64;
    float w0 = wrow[c],     w1 = wrow[c + 1];
    float w8 = wrow[c + 8], w9 = wrow[c + 9];
    __half h0 = __float2half_rn(w0), h1 = __float2half_rn(w1);
    __half h8 = __float2half_rn(w8), h9 = __float2half_rn(w9);
    uint4 v;
    v.x = packh2(__half2float(h0), __half2float(h1));   // hi, cols +0..7
    v.y = packh2(__half2float(h8), __half2float(h9));   // hi, cols +8..15
    v.z = packh2(w0 - __half2float(h0), w1 - __half2float(h1));  // lo
    v.w = packh2(w8 - __half2float(h8), w9 - __half2float(h9));  // lo
    g_bf[idx] = v;
}

// pack 8 fp32 -> single fp16 plane uint4
__device__ __forceinline__ uint4 pack8h(const float* f) {
    return make_uint4(packh2(f[0], f[1]), packh2(f[2], f[3]),
                      packh2(f[4], f[5]), packh2(f[6], f[7]));
}

__device__ __forceinline__ void ldm_x4(u32 a, u32* r) {
    asm volatile("ldmatrix.sync.aligned.m8n8.x4.shared.b16 {%0,%1,%2,%3}, [%4];"
        : "=r"(r[0]), "=r"(r[1]), "=r"(r[2]), "=r"(r[3]) : "r"(a));
}
__device__ __forceinline__ void mma16816(float* d, const u32* a,
                                         u32 b0, u32 b1) {
    asm volatile(
        "mma.sync.aligned.m16n8k16.row.col.f32.f16.f16.f32 "
        "{%0,%1,%2,%3},{%4,%5,%6,%7},{%8,%9},{%0,%1,%2,%3};"
        : "+f"(d[0]), "+f"(d[1]), "+f"(d[2]), "+f"(d[3])
        : "r"(a[0]), "r"(a[1]), "r"(a[2]), "r"(a[3]), "r"(b0), "r"(b1));
}

__global__ void __launch_bounds__(NTHREADS, 2)
dag_kernel(const float* __restrict__ x0, const float* __restrict__ x1,
           float* __restrict__ out) {
    extern __shared__ __align__(1024) unsigned char sm[];
    u32 smb;
    asm("{.reg .u64 t; cvta.to.shared.u64 t, %1; cvt.u32.u64 %0, t;}"
        : "=r"(smb) : "l"(sm));

    const int tid  = threadIdx.x;
    const int lane = tid & 31;
    const int wid  = tid >> 5;
    const int b    = blockIdx.x >> 4;
    const int p0   = (blockIdx.x & 15) * 64;

    // --- stage x0 -> slot3, x1 -> slot4 (2 threads per position row)
    {
        const int half = tid >> 7;
        const int r    = tid & 127;
        const int p    = r >> 1;
        const int ci   = r & 1;
        const float* gx = (half ? x1 : x0) + b * 65536 + p0 + p;
        unsigned char* slot = sm + (3 + half) * ASLOT;
        const u32 xm = (u32)((p & 7) << 4);
#pragma unroll
        for (int i = 0; i < 4; ++i) {
            const int ii = ci * 4 + i;
            float f[8];
#pragma unroll
            for (int j = 0; j < 8; ++j) f[j] = gx[(ii * 8 + j) * 1024];
            u32 off = (u32)(p * 128) + (((u32)(ii * 16)) ^ xm);
            *reinterpret_cast<uint4*>(slot + off) = pack8h(f);
        }
    }
    __syncthreads();

    // --- warp mapping: 2m x 2n x 2k; warp = 32 pos x 32 out, half K
    const int kh = wid >> 2;
    const int m0 = (wid & 1) * 32;
    const int n0 = ((wid >> 1) & 1) * 32;
    const int arow  = m0 + (lane & 15);
    const int acolb = (lane >> 4) * 16;
    const u32 axm = (u32)((lane & 7) << 4);
    const int prow = lane >> 2;
    const int pcol = (lane & 3) * 2;
    const u32 pxm = (u32)(prow << 4);
    unsigned char* scr = sm + SM_SCR;

    float d[2][4][4];

#pragma unroll 1
    for (int g = 0; g < NG; ++g) {
        if (c_st[g]) {
#pragma unroll
            for (int mt = 0; mt < 2; ++mt)
#pragma unroll
                for (int nt = 0; nt < 4; ++nt)
#pragma unroll
                    for (int e = 0; e < 4; ++e) d[mt][nt][e] = 0.f;
        }
        // --- B fragments straight from global (identical across blocks ->
        //     L1/L2 resident). [g][kc][q][lane], kc = kh*2+kk, q = n0/8+nt.
        uint4 bf0[4], bf1[4];
        {
            const uint4* bp = g_bf + (((g * 4 + kh * 2) * 8 + (n0 >> 3)) * 32)
                              + lane;
#pragma unroll
            for (int nt = 0; nt < 4; ++nt) bf0[nt] = bp[nt * 32];
#pragma unroll
            for (int nt = 0; nt < 4; ++nt) bf1[nt] = bp[(8 + nt) * 32];
        }
        // --- GEMM (k-half): d += A x (W_hi + W_lo)^T, 2 passes
        {
            const u32 a_b = smb + c_in[g] * ASLOT;
#pragma unroll
            for (int kk = 0; kk < 2; ++kk) {
                const int kc = kh * 2 + kk;
                const u32 akb = ((u32)(acolb + kc * 32)) ^ axm;
                const uint4* bfk = kk ? bf1 : bf0;
                u32 ah[2][4];
#pragma unroll
                for (int mt = 0; mt < 2; ++mt)
                    ldm_x4(a_b + (u32)((arow + mt * 16) * 128) + akb, ah[mt]);
                // pass 1: A * W_hi
#pragma unroll
                for (int mt = 0; mt < 2; ++mt)
#pragma unroll
                    for (int nt = 0; nt < 4; ++nt)
                        mma16816(d[mt][nt], ah[mt], bfk[nt].x, bfk[nt].y);
                // pass 2: A * W_lo
#pragma unroll
                for (int mt = 0; mt < 2; ++mt)
#pragma unroll
                    for (int nt = 0; nt < 4; ++nt)
                        mma16816(d[mt][nt], ah[mt], bfk[nt].z, bfk[nt].w);
            }
        }
        // --- state finished: reduce k-halves via scratch, raw -> global,
        //     relu (fp16) -> A slot. Only 2 barriers per fin.
        {
            const int f = c_fin[g];
            if (f >= 0) {
                if (kh) {                           // upper K half: dump raw
#pragma unroll
                    for (int mt = 0; mt < 2; ++mt)
#pragma unroll
                        for (int nt = 0; nt < 4; ++nt) {
                            const int p = m0 + mt * 16 + prow;
                            const int o = n0 + nt * 8 + pcol;
                            const u32 cb = ((u32)(o * 4)) ^ ((u32)(prow << 5));
                            *reinterpret_cast<float2*>(scr + p * 256 + cb) =
                                make_float2(d[mt][nt][0], d[mt][nt][1]);
                            *reinterpret_cast<float2*>(scr + (p + 8) * 256 + cb) =
                                make_float2(d[mt][nt][2], d[mt][nt][3]);
                        }
                }
                __syncthreads();                    // dump visible
                if (!kh) {
#pragma unroll
                    for (int mt = 0; mt < 2; ++mt)
#pragma unroll
                        for (int nt = 0; nt < 4; ++nt) {
                            const int p = m0 + mt * 16 + prow;
                            const int o = n0 + nt * 8 + pcol;
                            const u32 cb = ((u32)(o * 4)) ^ ((u32)(prow << 5));
                            float2 u = *reinterpret_cast<const float2*>(
                                           scr + p * 256 + cb);
                            float2 v = *reinterpret_cast<const float2*>(
                                           scr + (p + 8) * 256 + cb);
                            d[mt][nt][0] += u.x; d[mt][nt][1] += u.y;
                            d[mt][nt][2] += v.x; d[mt][nt][3] += v.y;
                        }
                    if (f >= 2) {                   // raw node -> global
                        const int node = (f == 5) ? 3 : (f - 2);
                        float* gp = out + b * 262144 + node * 65536 + p0;
#pragma unroll
                        for (int mt = 0; mt < 2; ++mt)
#pragma unroll
                            for (int nt = 0; nt < 4; ++nt) {
                                const int o = n0 + nt * 8 + pcol;
                                const int p = m0 + mt * 16 + prow;
                                gp[o * 1024 + p]           = d[mt][nt][0];
                                gp[(o + 1) * 1024 + p]     = d[mt][nt][1];
                                gp[o * 1024 + p + 8]       = d[mt][nt][2];
                                gp[(o + 1) * 1024 + p + 8] = d[mt][nt][3];
                            }
                    }
                    if (f <= 4) {                   // relu fp16 -> A slot f
                        unsigned char* sd = sm + f * ASLOT;
#pragma unroll
                        for (int mt = 0; mt < 2; ++mt)
#pragma unroll
                            for (int nt = 0; nt < 4; ++nt) {
                                const int p = m0 + mt * 16 + prow;
                                const int c = n0 + nt * 8 + pcol;
                                const u32 cb = ((u32)(c * 2)) ^ pxm;
                                u32 hp = packh2(fmaxf(d[mt][nt][0], 0.f),
                                                fmaxf(d[mt][nt][1], 0.f));
                                *reinterpret_cast<u32*>(
                                    sd + (u32)(p * 128) + cb) = hp;
                                hp = packh2(fmaxf(d[mt][nt][2], 0.f),
                                            fmaxf(d[mt][nt][3], 0.f));
                                *reinterpret_cast<u32*>(
                                    sd + (u32)((p + 8) * 128) + cb) = hp;
                            }
                    }
                }
                __syncthreads();                    // slot/scratch safe
            }
        }
    }
}

extern "C" void kernel_launch(void* const* d_in, const int* in_sizes, int n_in,
                              void* d_out, int out_size) {
    const float* x0    = (const float*)d_in[0];
    const float* x1    = (const float*)d_in[1];
    const float* Wpre  = (const float*)d_in[2];
    const float* Wedge = (const float*)d_in[3];
    float* out = (float*)d_out;

    prep_weights_kernel<<<64, 256>>>(Wpre, Wedge);

    cudaFuncSetAttribute(dag_kernel,
                         cudaFuncAttributeMaxDynamicSharedMemorySize,
                         SMEM_BYTES);
    dag_kernel<<<1024, NTHREADS, SMEM_BYTES>>>(x0, x1, out);
}

// round 15
// speedup vs baseline: 1.6824x; 1.0733x over previous
#include <cuda_runtime.h>
#include <cuda_fp16.h>

typedef unsigned int u32;

#define NG 16
#define NTHREADS 256

// smem: 5 A slots (64 rows x 128B fp16). No scratch (no split-K).
#define ASLOT   8192
#define SMEM_BYTES (5 * ASLOT)         // 40960 -> 3 blocks/SM

// schedule (validated): slots 0=s0 1=s1 2=n0 3=n1 4=n2; x0->3, x1->4
__constant__ int c_in[NG]  = {3,4, 0,1, 0,1,2, 0,1,2,3, 0,1,2,3,4};
__constant__ int c_st[NG]  = {1,1, 1,0, 1,0,0, 1,0,0,0, 1,0,0,0,0};
__constant__ int c_fin[NG] = {0,1, -1,2, -1,-1,3, -1,-1,-1,4, -1,-1,-1,-1,5};

// B fragments (single fp16 plane), mma lane order:
// [g][q][lane] -> 2 x uint4: {kc0.b0,kc0.b1,kc1.b0,kc1.b1},{kc2...,kc3...}
__device__ __align__(16) uint4 g_bf[NG * 8 * 32 * 2];   // 64 KB

__device__ __forceinline__ u32 packh2(float a, float b) {
    __half2 h = __floats2half2_rn(a, b);
    return *reinterpret_cast<u32*>(&h);
}

__global__ void prep_weights_kernel(const float* __restrict__ Wpre,
                                    const float* __restrict__ Wedge) {
    int idx = blockIdx.x * blockDim.x + threadIdx.x;   // (g*8+q)*32+lane
    if (idx >= NG * 8 * 32) return;
    const int lane = idx & 31;
    const int q    = (idx >> 5) & 7;
    const int g    = idx >> 8;
    const int o = q * 8 + (lane >> 2);           // output channel (B row)
    const float* wrow = (g < 2 ? Wpre + g * 4096 : Wedge + (g - 2) * 4096)
                        + o * 64;
    u32 bw[8];
#pragma unroll
    for (int kc = 0; kc < 4; ++kc) {
        const int c = kc * 16 + (lane & 3) * 2;  // input channel (B col/k)
        bw[kc * 2 + 0] = packh2(wrow[c],     wrow[c + 1]);      // k rows 0-7
        bw[kc * 2 + 1] = packh2(wrow[c + 8], wrow[c + 9]);      // k rows 8-15
    }
    g_bf[idx * 2 + 0] = make_uint4(bw[0], bw[1], bw[2], bw[3]);
    g_bf[idx * 2 + 1] = make_uint4(bw[4], bw[5], bw[6], bw[7]);
}

// pack 8 fp32 -> single fp16 plane uint4
__device__ __forceinline__ uint4 pack8h(const float* f) {
    return make_uint4(packh2(f[0], f[1]), packh2(f[2], f[3]),
                      packh2(f[4], f[5]), packh2(f[6], f[7]));
}

__device__ __forceinline__ void ldm_x4(u32 a, u32* r) {
    asm volatile("ldmatrix.sync.aligned.m8n8.x4.shared.b16 {%0,%1,%2,%3}, [%4];"
        : "=r"(r[0]), "=r"(r[1]), "=r"(r[2]), "=r"(r[3]) : "r"(a));
}
__device__ __forceinline__ void mma16816(float* d, const u32* a,
                                         u32 b0, u32 b1) {
    asm volatile(
        "mma.sync.aligned.m16n8k16.row.col.f32.f16.f16.f32 "
        "{%0,%1,%2,%3},{%4,%5,%6,%7},{%8,%9},{%0,%1,%2,%3};"
        : "+f"(d[0]), "+f"(d[1]), "+f"(d[2]), "+f"(d[3])
        : "r"(a[0]), "r"(a[1]), "r"(a[2]), "r"(a[3]), "r"(b0), "r"(b1));
}

__global__ void __launch_bounds__(NTHREADS, 3)
dag_kernel(const float* __restrict__ x0, const float* __restrict__ x1,
           float* __restrict__ out) {
    extern __shared__ __align__(1024) unsigned char sm[];
    u32 smb;
    asm("{.reg .u64 t; cvta.to.shared.u64 t, %1; cvt.u32.u64 %0, t;}"
        : "=r"(smb) : "l"(sm));

    const int tid  = threadIdx.x;
    const int lane = tid & 31;
    const int wid  = tid >> 5;
    const int b    = blockIdx.x >> 4;
    const int p0   = (blockIdx.x & 15) * 64;

    // --- stage x0 -> slot3, x1 -> slot4 (2 threads per position row)
    {
        const int half = tid >> 7;
        const int r    = tid & 127;
        const int p    = r >> 1;
        const int ci   = r & 1;
        const float* gx = (half ? x1 : x0) + b * 65536 + p0 + p;
        unsigned char* slot = sm + (3 + half) * ASLOT;
        const u32 xm = (u32)((p & 7) << 4);
#pragma unroll
        for (int i = 0; i < 4; ++i) {
            const int ii = ci * 4 + i;
            float f[8];
#pragma unroll
            for (int j = 0; j < 8; ++j) f[j] = gx[(ii * 8 + j) * 1024];
            u32 off = (u32)(p * 128) + (((u32)(ii * 16)) ^ xm);
            *reinterpret_cast<uint4*>(slot + off) = pack8h(f);
        }
    }
    __syncthreads();

    // --- warp mapping: 2m x 4n, FULL K per warp; warp = 32 pos x 16 out
    const int m0 = (wid & 1) * 32;
    const int n0 = (wid >> 1) * 16;              // q0 = n0/8
    const int arow  = m0 + (lane & 15);
    const int acolb = (lane >> 4) * 16;
    const u32 axm = (u32)((lane & 7) << 4);
    const int prow = lane >> 2;
    const int pcol = (lane & 3) * 2;
    const u32 pxm = (u32)(prow << 4);

    float d[2][2][4];

#pragma unroll 1
    for (int g = 0; g < NG; ++g) {
        if (c_st[g]) {
#pragma unroll
            for (int mt = 0; mt < 2; ++mt)
#pragma unroll
                for (int nt = 0; nt < 2; ++nt)
#pragma unroll
                    for (int e = 0; e < 4; ++e) d[mt][nt][e] = 0.f;
        }
        // --- B fragments straight from global (L1/L2 resident; identical
        //     addresses across blocks). bf[nt][pair]
        uint4 bf[2][2];
        {
            const uint4* bp = g_bf + (((g * 8) + (n0 >> 3)) * 32 + lane) * 2;
            bf[0][0] = bp[0];  bf[0][1] = bp[1];
            bf[1][0] = bp[64]; bf[1][1] = bp[65];   // next octet: +32 lanes *2
        }
        // --- GEMM: d += A x W^T, single fp16 pass, full K (4 k-chunks)
        {
            const u32 a_b = smb + c_in[g] * ASLOT;
#pragma unroll
            for (int kk = 0; kk < 4; ++kk) {
                const u32 akb = ((u32)(acolb + kk * 32)) ^ axm;
                u32 ah[2][4];
#pragma unroll
                for (int mt = 0; mt < 2; ++mt)
                    ldm_x4(a_b + (u32)((arow + mt * 16) * 128) + akb, ah[mt]);
#pragma unroll
                for (int mt = 0; mt < 2; ++mt)
#pragma unroll
                    for (int nt = 0; nt < 2; ++nt) {
                        const uint4& v = bf[nt][kk >> 1];
                        const u32 b0 = (kk & 1) ? v.z : v.x;
                        const u32 b1 = (kk & 1) ? v.w : v.y;
                        mma16816(d[mt][nt], ah[mt], b0, b1);
                    }
            }
        }
        // --- state finished: raw -> global (nodes), relu fp16 -> A slot.
        //     Full-K warps own disjoint tiles: ONE barrier per fin.
        {
            const int f = c_fin[g];
            if (f >= 0) {
                if (f >= 2) {                   // raw node -> global
                    const int node = (f == 5) ? 3 : (f - 2);
                    float* gp = out + b * 262144 + node * 65536 + p0;
#pragma unroll
                    for (int mt = 0; mt < 2; ++mt)
#pragma unroll
                        for (int nt = 0; nt < 2; ++nt) {
                            const int o = n0 + nt * 8 + pcol;
                            const int p = m0 + mt * 16 + prow;
                            gp[o * 1024 + p]           = d[mt][nt][0];
                            gp[(o + 1) * 1024 + p]     = d[mt][nt][1];
                            gp[o * 1024 + p + 8]       = d[mt][nt][2];
                            gp[(o + 1) * 1024 + p + 8] = d[mt][nt][3];
                        }
                }
                if (f <= 4) {                   // relu fp16 -> A slot f
                    unsigned char* sd = sm + f * ASLOT;
#pragma unroll
                    for (int mt = 0; mt < 2; ++mt)
#pragma unroll
                        for (int nt = 0; nt < 2; ++nt) {
                            const int p = m0 + mt * 16 + prow;
                            const int c = n0 + nt * 8 + pcol;
                            const u32 cb = ((u32)(c * 2)) ^ pxm;
                            u32 hp = packh2(fmaxf(d[mt][nt][0], 0.f),
                                            fmaxf(d[mt][nt][1], 0.f));
                            *reinterpret_cast<u32*>(
                                sd + (u32)(p * 128) + cb) = hp;
                            hp = packh2(fmaxf(d[mt][nt][2], 0.f),
                                        fmaxf(d[mt][nt][3], 0.f));
                            *reinterpret_cast<u32*>(
                                sd + (u32)((p + 8) * 128) + cb) = hp;
                        }
                }
                __syncthreads();                // slot ready for consumers
            }
        }
    }
}

extern "C" void kernel_launch(void* const* d_in, const int* in_sizes, int n_in,
                              void* d_out, int out_size) {
    const float* x0    = (const float*)d_in[0];
    const float* x1    = (const float*)d_in[1];
    const float* Wpre  = (const float*)d_in[2];
    const float* Wedge = (const float*)d_in[3];
    float* out = (float*)d_out;

    prep_weights_kernel<<<16, 256>>>(Wpre, Wedge);

    cudaFuncSetAttribute(dag_kernel,
                         cudaFuncAttributeMaxDynamicSharedMemorySize,
                         SMEM_BYTES);
    dag_kernel<<<1024, NTHREADS, SMEM_BYTES>>>(x0, x1, out);
}

// round 16
// speedup vs baseline: 1.8715x; 1.1124x over previous
#include <cuda_runtime.h>
#include <cuda_fp16.h>

typedef unsigned int u32;

#define NG 16
#define NTHREADS 256

// smem: 5 A slots (128 rows x 128B fp16)
#define ASLOT   16384
#define SMEM_BYTES (5 * ASLOT)         // 81920 -> 2 blocks/SM

// schedule (validated): slots 0=s0 1=s1 2=n0 3=n1 4=n2; x0->3, x1->4
__constant__ int c_in[NG]  = {3,4, 0,1, 0,1,2, 0,1,2,3, 0,1,2,3,4};
__constant__ int c_st[NG]  = {1,1, 1,0, 1,0,0, 1,0,0,0, 1,0,0,0,0};
__constant__ int c_fin[NG] = {0,1, -1,2, -1,-1,3, -1,-1,-1,4, -1,-1,-1,-1,5};

// B fragments (single fp16 plane), mma lane order:
// [g][q][lane] -> 2 x uint4: {kc0.b0,kc0.b1,kc1.b0,kc1.b1},{kc2..,kc3..}
__device__ __align__(16) uint4 g_bf[NG * 8 * 32 * 2];   // 64 KB

__device__ __forceinline__ u32 packh2(float a, float b) {
    __half2 h = __floats2half2_rn(a, b);
    return *reinterpret_cast<u32*>(&h);
}

__global__ void prep_weights_kernel(const float* __restrict__ Wpre,
                                    const float* __restrict__ Wedge) {
    int idx = blockIdx.x * blockDim.x + threadIdx.x;   // (g*8+q)*32+lane
    if (idx >= NG * 8 * 32) return;
    const int lane = idx & 31;
    const int q    = (idx >> 5) & 7;
    const int g    = idx >> 8;
    const int o = q * 8 + (lane >> 2);
    const float* wrow = (g < 2 ? Wpre + g * 4096 : Wedge + (g - 2) * 4096)
                        + o * 64;
    u32 bw[8];
#pragma unroll
    for (int kc = 0; kc < 4; ++kc) {
        const int c = kc * 16 + (lane & 3) * 2;
        bw[kc * 2 + 0] = packh2(wrow[c],     wrow[c + 1]);
        bw[kc * 2 + 1] = packh2(wrow[c + 8], wrow[c + 9]);
    }
    g_bf[idx * 2 + 0] = make_uint4(bw[0], bw[1], bw[2], bw[3]);
    g_bf[idx * 2 + 1] = make_uint4(bw[4], bw[5], bw[6], bw[7]);
}

__device__ __forceinline__ uint4 pack8h(const float* f) {
    return make_uint4(packh2(f[0], f[1]), packh2(f[2], f[3]),
                      packh2(f[4], f[5]), packh2(f[6], f[7]));
}

__device__ __forceinline__ void ldm_x4(u32 a, u32* r) {
    asm volatile("ldmatrix.sync.aligned.m8n8.x4.shared.b16 {%0,%1,%2,%3}, [%4];"
        : "=r"(r[0]), "=r"(r[1]), "=r"(r[2]), "=r"(r[3]) : "r"(a));
}
__device__ __forceinline__ void mma16816(float* d, const u32* a,
                                         u32 b0, u32 b1) {
    asm volatile(
        "mma.sync.aligned.m16n8k16.row.col.f32.f16.f16.f32 "
        "{%0,%1,%2,%3},{%4,%5,%6,%7},{%8,%9},{%0,%1,%2,%3};"
        : "+f"(d[0]), "+f"(d[1]), "+f"(d[2]), "+f"(d[3])
        : "r"(a[0]), "r"(a[1]), "r"(a[2]), "r"(a[3]), "r"(b0), "r"(b1));
}

__global__ void __launch_bounds__(NTHREADS, 2)
dag_kernel(const float* __restrict__ x0, const float* __restrict__ x1,
           float* __restrict__ out) {
    extern __shared__ __align__(1024) unsigned char sm[];
    u32 smb;
    asm("{.reg .u64 t; cvta.to.shared.u64 t, %1; cvt.u32.u64 %0, t;}"
        : "=r"(smb) : "l"(sm));

    const int tid  = threadIdx.x;
    const int lane = tid & 31;
    const int wid  = tid >> 5;
    const int b    = blockIdx.x >> 3;
    const int p0   = (blockIdx.x & 7) * 128;

    // --- stage x0 -> slot3, x1 -> slot4 (1 thread per position row)
    {
        const int half = tid >> 7;                 // 0: x0, 1: x1
        const int p    = tid & 127;
        const float* gx = (half ? x1 : x0) + b * 65536 + p0 + p;
        unsigned char* slot = sm + (3 + half) * ASLOT;
        const u32 xm = (u32)((p & 7) << 4);
#pragma unroll
        for (int ii = 0; ii < 8; ++ii) {
            float f[8];
#pragma unroll
            for (int j = 0; j < 8; ++j) f[j] = gx[(ii * 8 + j) * 1024];
            u32 off = (u32)(p * 128) + (((u32)(ii * 16)) ^ xm);
            *reinterpret_cast<uint4*>(slot + off) = pack8h(f);
        }
    }
    __syncthreads();

    // --- warp mapping: 4m x 2n, FULL K; warp = 32 pos x 32 out
    const int m0 = (wid & 3) * 32;
    const int n0 = (wid >> 2) * 32;              // octets n0/8 .. n0/8+3
    const int arow  = m0 + (lane & 15);
    const int acolb = (lane >> 4) * 16;
    const u32 axm = (u32)((lane & 7) << 4);
    const int prow = lane >> 2;
    const int pcol = (lane & 3) * 2;
    const u32 pxm = (u32)(prow << 4);

    float d[2][4][4];

#pragma unroll 1
    for (int g = 0; g < NG; ++g) {
        if (c_st[g]) {
#pragma unroll
            for (int mt = 0; mt < 2; ++mt)
#pragma unroll
                for (int nt = 0; nt < 4; ++nt)
#pragma unroll
                    for (int e = 0; e < 4; ++e) d[mt][nt][e] = 0.f;
        }
        // --- B fragments from global (L1/L2 resident): 4 octets x 2 pairs
        uint4 bf[4][2];
        {
            const uint4* bp = g_bf + (((g * 8) + (n0 >> 3)) * 32 + lane) * 2;
#pragma unroll
            for (int nt = 0; nt < 4; ++nt) {
                bf[nt][0] = bp[nt * 64];
                bf[nt][1] = bp[nt * 64 + 1];
            }
        }
        // --- GEMM: d += A x W^T, single fp16 pass, full K
        {
            const u32 a_b = smb + c_in[g] * ASLOT;
#pragma unroll
            for (int kk = 0; kk < 4; ++kk) {
                const u32 akb = ((u32)(acolb + kk * 32)) ^ axm;
                u32 ah[2][4];
#pragma unroll
                for (int mt = 0; mt < 2; ++mt)
                    ldm_x4(a_b + (u32)((arow + mt * 16) * 128) + akb, ah[mt]);
#pragma unroll
                for (int mt = 0; mt < 2; ++mt)
#pragma unroll
                    for (int nt = 0; nt < 4; ++nt) {
                        const uint4& v = bf[nt][kk >> 1];
                        const u32 b0 = (kk & 1) ? v.z : v.x;
                        const u32 b1 = (kk & 1) ? v.w : v.y;
                        mma16816(d[mt][nt], ah[mt], b0, b1);
                    }
            }
        }
        // --- state finished: raw -> global (nodes), relu fp16 -> A slot.
        //     Warps own disjoint tiles: ONE barrier per fin.
        {
            const int f = c_fin[g];
            if (f >= 0) {
                if (f >= 2) {                   // raw node -> global
                    const int node = (f == 5) ? 3 : (f - 2);
                    float* gp = out + b * 262144 + node * 65536 + p0;
#pragma unroll
                    for (int mt = 0; mt < 2; ++mt)
#pragma unroll
                        for (int nt = 0; nt < 4; ++nt) {
                            const int o = n0 + nt * 8 + pcol;
                            const int p = m0 + mt * 16 + prow;
                            gp[o * 1024 + p]           = d[mt][nt][0];
                            gp[(o + 1) * 1024 + p]     = d[mt][nt][1];
                            gp[o * 1024 + p + 8]       = d[mt][nt][2];
                            gp[(o + 1) * 1024 + p + 8] = d[mt][nt][3];
                        }
                }
                if (f <= 4) {                   // relu fp16 -> A slot f
                    unsigned char* sd = sm + f * ASLOT;
#pragma unroll
                    for (int mt = 0; mt < 2; ++mt)
#pragma unroll
                        for (int nt = 0; nt < 4; ++nt) {
                            const int p = m0 + mt * 16 + prow;
                            const int c = n0 + nt * 8 + pcol;
                            const u32 cb = ((u32)(c * 2)) ^ pxm;
                            u32 hp = packh2(fmaxf(d[mt][nt][0], 0.f),
                                            fmaxf(d[mt][nt][1], 0.f));
                            *reinterpret_cast<u32*>(
                                sd + (u32)(p * 128) + cb) = hp;
                            hp = packh2(fmaxf(d[mt][nt][2], 0.f),
                                        fmaxf(d[mt][nt][3], 0.f));
                            *reinterpret_cast<u32*>(
                                sd + (u32)((p + 8) * 128) + cb) = hp;
                        }
                }
                __syncthreads();                // slot ready for consumers
            }
        }
    }
}

extern "C" void kernel_launch(void* const* d_in, const int* in_sizes, int n_in,
                              void* d_out, int out_size) {
    const float* x0    = (const float*)d_in[0];
    const float* x1    = (const float*)d_in[1];
    const float* Wpre  = (const float*)d_in[2];
    const float* Wedge = (const float*)d_in[3];
    float* out = (float*)d_out;

    prep_weights_kernel<<<16, 256>>>(Wpre, Wedge);

    cudaFuncSetAttribute(dag_kernel,
                         cudaFuncAttributeMaxDynamicSharedMemorySize,
                         SMEM_BYTES);
    dag_kernel<<<512, NTHREADS, SMEM_BYTES>>>(x0, x1, out);
}

// round 17
// speedup vs baseline: 1.9468x; 1.0402x over previous
#include <cuda_runtime.h>
#include <cuda_fp16.h>

typedef unsigned int u32;

#define NG 16
#define NTHREADS 256

// smem: 5 A slots (128 rows x 128B fp16)
#define ASLOT   16384
#define SMEM_BYTES (5 * ASLOT)         // 81920 -> 2 blocks/SM

// B fragments (single fp16 plane), mma lane order:
// [g][q][lane] -> 2 x uint4: {kc0.b0,kc0.b1,kc1.b0,kc1.b1},{kc2..,kc3..}
__device__ __align__(16) uint4 g_bf[NG * 8 * 32 * 2];   // 64 KB

__device__ __forceinline__ u32 packh2(float a, float b) {
    __half2 h = __floats2half2_rn(a, b);
    return *reinterpret_cast<u32*>(&h);
}

__global__ void prep_weights_kernel(const float* __restrict__ Wpre,
                                    const float* __restrict__ Wedge) {
    int idx = blockIdx.x * blockDim.x + threadIdx.x;   // (g*8+q)*32+lane
    if (idx >= NG * 8 * 32) return;
    const int lane = idx & 31;
    const int q    = (idx >> 5) & 7;
    const int g    = idx >> 8;
    const int o = q * 8 + (lane >> 2);
    const float* wrow = (g < 2 ? Wpre + g * 4096 : Wedge + (g - 2) * 4096)
                        + o * 64;
    u32 bw[8];
#pragma unroll
    for (int kc = 0; kc < 4; ++kc) {
        const int c = kc * 16 + (lane & 3) * 2;
        bw[kc * 2 + 0] = packh2(wrow[c],     wrow[c + 1]);
        bw[kc * 2 + 1] = packh2(wrow[c + 8], wrow[c + 9]);
    }
    g_bf[idx * 2 + 0] = make_uint4(bw[0], bw[1], bw[2], bw[3]);
    g_bf[idx * 2 + 1] = make_uint4(bw[4], bw[5], bw[6], bw[7]);
}

__device__ __forceinline__ uint4 pack8h(const float* f) {
    return make_uint4(packh2(f[0], f[1]), packh2(f[2], f[3]),
                      packh2(f[4], f[5]), packh2(f[6], f[7]));
}

__device__ __forceinline__ void ldm_x4(u32 a, u32* r) {
    asm volatile("ldmatrix.sync.aligned.m8n8.x4.shared.b16 {%0,%1,%2,%3}, [%4];"
        : "=r"(r[0]), "=r"(r[1]), "=r"(r[2]), "=r"(r[3]) : "r"(a));
}
__device__ __forceinline__ void mma16816(float* d, const u32* a,
                                         u32 b0, u32 b1) {
    asm volatile(
        "mma.sync.aligned.m16n8k16.row.col.f32.f16.f16.f32 "
        "{%0,%1,%2,%3},{%4,%5,%6,%7},{%8,%9},{%0,%1,%2,%3};"
        : "+f"(d[0]), "+f"(d[1]), "+f"(d[2]), "+f"(d[3])
        : "r"(a[0]), "r"(a[1]), "r"(a[2]), "r"(a[3]), "r"(b0), "r"(b1));
}

__global__ void __launch_bounds__(NTHREADS, 2)
dag_kernel(const float* __restrict__ x0, const float* __restrict__ x1,
           float* __restrict__ out) {
    extern __shared__ __align__(1024) unsigned char sm[];
    u32 smb;
    asm("{.reg .u64 t; cvta.to.shared.u64 t, %1; cvt.u32.u64 %0, t;}"
        : "=r"(smb) : "l"(sm));

    const int tid  = threadIdx.x;
    const int lane = tid & 31;
    const int wid  = tid >> 5;
    const int b    = blockIdx.x >> 3;
    const int p0   = (blockIdx.x & 7) * 128;

    // --- stage x0 -> slot3, x1 -> slot4 (1 thread per position row)
    {
        const int half = tid >> 7;                 // 0: x0, 1: x1
        const int p    = tid & 127;
        const float* gx = (half ? x1 : x0) + b * 65536 + p0 + p;
        unsigned char* slot = sm + (3 + half) * ASLOT;
        const u32 xm = (u32)((p & 7) << 4);
#pragma unroll
        for (int ii = 0; ii < 8; ++ii) {
            float f[8];
#pragma unroll
            for (int j = 0; j < 8; ++j) f[j] = gx[(ii * 8 + j) * 1024];
            u32 off = (u32)(p * 128) + (((u32)(ii * 16)) ^ xm);
            *reinterpret_cast<uint4*>(slot + off) = pack8h(f);
        }
    }
    __syncthreads();

    // --- warp mapping: 4m x 2n, FULL K; warp = 32 pos x 32 out
    const int m0 = (wid & 3) * 32;
    const int n0 = (wid >> 2) * 32;
    const int arow  = m0 + (lane & 15);
    const int acolb = (lane >> 4) * 16;
    const u32 axm = (u32)((lane & 7) << 4);
    const int prow = lane >> 2;
    const int pcol = (lane & 3) * 2;
    const u32 pxm = (u32)(prow << 4);

    float d[2][4][4];

    // compile-time schedule: slots 0=s0 1=s1 2=n0 3=n1 4=n2; x0->3, x1->4
    constexpr int L_in[NG]  = {3,4, 0,1, 0,1,2, 0,1,2,3, 0,1,2,3,4};
    constexpr int L_st[NG]  = {1,1, 1,0, 1,0,0, 1,0,0,0, 1,0,0,0,0};
    constexpr int L_fin[NG] = {0,1, -1,2, -1,-1,3, -1,-1,-1,4, -1,-1,-1,-1,5};

#pragma unroll
    for (int g = 0; g < NG; ++g) {
        if (L_st[g]) {
#pragma unroll
            for (int mt = 0; mt < 2; ++mt)
#pragma unroll
                for (int nt = 0; nt < 4; ++nt)
#pragma unroll
                    for (int e = 0; e < 4; ++e) d[mt][nt][e] = 0.f;
        }
        // --- B fragments from global (L1/L2 resident); with the g-loop
        //     fully unrolled ptxas hoists these into the previous GEMM.
        uint4 bf[4][2];
        {
            const uint4* bp = g_bf + (((g * 8) + (n0 >> 3)) * 32 + lane) * 2;
#pragma unroll
            for (int nt = 0; nt < 4; ++nt) {
                bf[nt][0] = bp[nt * 64];
                bf[nt][1] = bp[nt * 64 + 1];
            }
        }
        // --- GEMM: d += A x W^T, single fp16 pass, full K.
        //     kk software pipeline: preload A for kk+1 during MMA of kk.
        {
            const u32 a_b = smb + L_in[g] * ASLOT;
            u32 ahA[2][4], ahB[2][4];
#pragma unroll
            for (int mt = 0; mt < 2; ++mt)
                ldm_x4(a_b + (u32)((arow + mt * 16) * 128)
                           + (((u32)acolb) ^ axm), ahA[mt]);
#pragma unroll
            for (int kk = 0; kk < 4; ++kk) {
                u32 (*cur)[4] = (kk & 1) ? ahB : ahA;
                u32 (*nxt)[4] = (kk & 1) ? ahA : ahB;
                if (kk < 3) {
                    const u32 akb = ((u32)(acolb + (kk + 1) * 32)) ^ axm;
#pragma unroll
                    for (int mt = 0; mt < 2; ++mt)
                        ldm_x4(a_b + (u32)((arow + mt * 16) * 128) + akb,
                               nxt[mt]);
                }
#pragma unroll
                for (int mt = 0; mt < 2; ++mt)
#pragma unroll
                    for (int nt = 0; nt < 4; ++nt) {
                        const uint4& v = bf[nt][kk >> 1];
                        const u32 b0 = (kk & 1) ? v.z : v.x;
                        const u32 b1 = (kk & 1) ? v.w : v.y;
                        mma16816(d[mt][nt], cur[mt], b0, b1);
                    }
            }
        }
        // --- state finished: raw -> global (nodes), relu fp16 -> A slot.
        {
            const int f = L_fin[g];
            if (f >= 0) {
                if (f >= 2) {                   // raw node -> global
                    const int node = (f == 5) ? 3 : (f - 2);
                    float* gp = out + b * 262144 + node * 65536 + p0;
#pragma unroll
                    for (int mt = 0; mt < 2; ++mt)
#pragma unroll
                        for (int nt = 0; nt < 4; ++nt) {
                            const int o = n0 + nt * 8 + pcol;
                            const int p = m0 + mt * 16 + prow;
                            gp[o * 1024 + p]           = d[mt][nt][0];
                            gp[(o + 1) * 1024 + p]     = d[mt][nt][1];
                            gp[o * 1024 + p + 8]       = d[mt][nt][2];
                            gp[(o + 1) * 1024 + p + 8] = d[mt][nt][3];
                        }
                }
                if (f <= 4) {                   // relu fp16 -> A slot f
                    unsigned char* sd = sm + f * ASLOT;
#pragma unroll
                    for (int mt = 0; mt < 2; ++mt)
#pragma unroll
                        for (int nt = 0; nt < 4; ++nt) {
                            const int p = m0 + mt * 16 + prow;
                            const int c = n0 + nt * 8 + pcol;
                            const u32 cb = ((u32)(c * 2)) ^ pxm;
                            u32 hp = packh2(fmaxf(d[mt][nt][0], 0.f),
                                            fmaxf(d[mt][nt][1], 0.f));
                            *reinterpret_cast<u32*>(
                                sd + (u32)(p * 128) + cb) = hp;
                            hp = packh2(fmaxf(d[mt][nt][2], 0.f),
                                        fmaxf(d[mt][nt][3], 0.f));
                            *reinterpret_cast<u32*>(
                                sd + (u32)((p + 8) * 128) + cb) = hp;
                        }
                }
                __syncthreads();                // slot ready for consumers
            }
        }
    }
}

extern "C" void kernel_launch(void* const* d_in, const int* in_sizes, int n_in,
                              void* d_out, int out_size) {
    const float* x0    = (const float*)d_in[0];
    const float* x1    = (const float*)d_in[1];
    const float* Wpre  = (const float*)d_in[2];
    const float* Wedge = (const float*)d_in[3];
    float* out = (float*)d_out;

    prep_weights_kernel<<<16, 256>>>(Wpre, Wedge);

    cudaFuncSetAttribute(dag_kernel,
                         cudaFuncAttributeMaxDynamicSharedMemorySize,
                         SMEM_BYTES);
    dag_kernel<<<512, NTHREADS, SMEM_BYTES>>>(x0, x1, out);
}